// round 1
// baseline (speedup 1.0000x reference)
#include <cuda_runtime.h>
#include <math.h>
#include <float.h>

#define KCOMP 32
#define DDIM  128
#define LDIM  4
#define TILE  192
#define TPB   192
#define XSTRIDE (TILE + 1)   // 193, conflict-free for lane-consecutive reads

// Precomputed per-component weights (device globals: no allocation allowed)
__device__ float4 g_WA[KCOMP * DDIM];   // {iD, iD*mu, Bp0, Bp1}
__device__ float2 g_WB[KCOMP * DDIM];   // {Bp2, Bp3}
__device__ float  g_cst[KCOMP];
__device__ float4 g_bm[KCOMP];          // bmup (U @ bmu)

// ---------------------------------------------------------------------------
// Stage A: per-component precompute. One block per component, 128 threads (=d).
// ---------------------------------------------------------------------------
__global__ void mfa_precompute(const float* __restrict__ MU,
                               const float* __restrict__ A,
                               const float* __restrict__ Dm,
                               const float* __restrict__ PI)
{
    const int k = blockIdx.x;
    const int d = threadIdx.x;   // 0..127

    __shared__ float  red[22][DDIM];
    __shared__ double rsum[22];
    __shared__ double sU[LDIM][LDIM];

    const float Dv = Dm[k * DDIM + d];
    const float iD = 1.0f / (Dv * Dv);
    const float mu = MU[k * DDIM + d];

    float a[LDIM], B[LDIM];
#pragma unroll
    for (int l = 0; l < LDIM; l++) {
        a[l] = A[(k * DDIM + d) * LDIM + l];
        B[l] = iD * a[l];
    }

    // Partial sums: 16 L_lm, 4 bmu_m, tc, sum log D^2
    int idx = 0;
#pragma unroll
    for (int l = 0; l < LDIM; l++)
#pragma unroll
        for (int m = 0; m < LDIM; m++)
            red[idx++][d] = a[l] * B[m];
#pragma unroll
    for (int m = 0; m < LDIM; m++)
        red[idx++][d] = mu * B[m];
    red[idx++][d] = iD * mu * mu;       // tc partial
    red[idx++][d] = 2.0f * logf(Dv);    // log D^2 partial
    __syncthreads();

    if (d < 22) {
        double s = 0.0;
        for (int i = 0; i < DDIM; i++) s += (double)red[d][i];
        rsum[d] = s;
    }
    __syncthreads();

    if (d == 0) {
        double Lm[LDIM][LDIM];
        for (int l = 0; l < LDIM; l++)
            for (int m = 0; m < LDIM; m++)
                Lm[l][m] = rsum[l * LDIM + m] + (l == m ? 1.0 : 0.0);
        double bmu[LDIM];
        for (int m = 0; m < LDIM; m++) bmu[m] = rsum[16 + m];
        const double tc  = rsum[20];
        const double sld = rsum[21];

        // Cholesky L = G G^T (lower)
        double G[LDIM][LDIM] = {};
        for (int i = 0; i < LDIM; i++) {
            for (int j = 0; j <= i; j++) {
                double s = Lm[i][j];
                for (int p = 0; p < j; p++) s -= G[i][p] * G[j][p];
                if (i == j) G[i][i] = sqrt(s);
                else        G[i][j] = s / G[j][j];
            }
        }
        double logdetL = 0.0;
        for (int i = 0; i < LDIM; i++) logdetL += 2.0 * log(G[i][i]);

        // U = G^{-1} (lower), so y^T L^{-1} y = ||U y||^2
        double U[LDIM][LDIM] = {};
        for (int j = 0; j < LDIM; j++) {
            U[j][j] = 1.0 / G[j][j];
            for (int i = j + 1; i < LDIM; i++) {
                double s = 0.0;
                for (int p = j; p < i; p++) s += G[i][p] * U[p][j];
                U[i][j] = -s / G[i][i];
            }
        }
        for (int l = 0; l < LDIM; l++)
            for (int m = 0; m < LDIM; m++)
                sU[l][m] = U[l][m];

        const double LOG2PI = 1.8378770664093454835606594728112;
        g_cst[k] = (float)((double)PI[k]
                  - 0.5 * ((double)DDIM * LOG2PI + logdetL + sld + tc));

        double bp[LDIM];
        for (int l = 0; l < LDIM; l++) {
            double s = 0.0;
            for (int m = 0; m <= l; m++) s += U[l][m] * bmu[m];
            bp[l] = s;
        }
        g_bm[k] = make_float4((float)bp[0], (float)bp[1], (float)bp[2], (float)bp[3]);
    }
    __syncthreads();

    // Bp[d][l] = sum_m U[l][m] * B[d][m]
    float Bp[LDIM];
#pragma unroll
    for (int l = 0; l < LDIM; l++) {
        double s = 0.0;
        for (int m = 0; m <= l; m++) s += sU[l][m] * (double)B[m];
        Bp[l] = (float)s;
    }
    g_WA[k * DDIM + d] = make_float4(iD, iD * mu, Bp[0], Bp[1]);
    g_WB[k * DDIM + d] = make_float2(Bp[2], Bp[3]);
}

// ---------------------------------------------------------------------------
// Stage B: main kernel. One thread per row; x tile transposed in shared,
// all weights resident in shared (warp-uniform broadcast reads).
// ---------------------------------------------------------------------------
__global__ void __launch_bounds__(TPB, 1)
mfa_main(const float* __restrict__ x, float* __restrict__ out, int N)
{
    extern __shared__ float smem[];
    float*  xs  = smem;                                     // DDIM * XSTRIDE
    float4* sWA = (float4*)(smem + DDIM * XSTRIDE);         // KCOMP*DDIM
    float2* sWB = (float2*)(sWA + KCOMP * DDIM);            // KCOMP*DDIM
    float*  sC  = (float*)(sWB + KCOMP * DDIM);             // KCOMP*5

    const int tid  = threadIdx.x;
    const int row0 = blockIdx.x * TILE;

    // Load weights into shared
    for (int i = tid; i < KCOMP * DDIM; i += TPB) {
        sWA[i] = g_WA[i];
        sWB[i] = g_WB[i];
    }
    if (tid < KCOMP) {
        sC[tid * 5 + 0] = g_cst[tid];
        float4 b = g_bm[tid];
        sC[tid * 5 + 1] = b.x; sC[tid * 5 + 2] = b.y;
        sC[tid * 5 + 3] = b.z; sC[tid * 5 + 4] = b.w;
    }

    // Load x tile transposed: xs[d][r], r = local row
    const int NQ = TILE * (DDIM / 4);   // float4s in tile
    for (int i = tid; i < NQ; i += TPB) {
        const int r = i >> 5;           // local row
        const int q = i & 31;           // d-quad
        const int row = row0 + r;
        float4 v = (row < N) ? __ldg((const float4*)x + (size_t)row * (DDIM / 4) + q)
                             : make_float4(0.f, 0.f, 0.f, 0.f);
        const int base = (q * 4) * XSTRIDE + r;
        xs[base + 0 * XSTRIDE] = v.x;
        xs[base + 1 * XSTRIDE] = v.y;
        xs[base + 2 * XSTRIDE] = v.z;
        xs[base + 3 * XSTRIDE] = v.w;
    }
    __syncthreads();

    const int row = row0 + tid;
    float mx = -FLT_MAX, sum = 0.f;

    for (int k = 0; k < KCOMP; k++) {
        const float4* wa = sWA + k * DDIM;
        const float2* wb = sWB + k * DDIM;
        float s1 = 0.f, s2 = 0.f, z0 = 0.f, z1 = 0.f, z2 = 0.f, z3 = 0.f;
#pragma unroll 8
        for (int d = 0; d < DDIM; d++) {
            const float xv = xs[d * XSTRIDE + tid];
            const float4 A4 = wa[d];
            const float2 B2 = wb[d];
            const float x2 = xv * xv;
            s1 = fmaf(A4.x, x2, s1);
            s2 = fmaf(A4.y, xv, s2);
            z0 = fmaf(A4.z, xv, z0);
            z1 = fmaf(A4.w, xv, z1);
            z2 = fmaf(B2.x, xv, z2);
            z3 = fmaf(B2.y, xv, z3);
        }
        const float cst = sC[k * 5 + 0];
        z0 -= sC[k * 5 + 1];
        z1 -= sC[k * 5 + 2];
        z2 -= sC[k * 5 + 3];
        z3 -= sC[k * 5 + 4];
        const float q2 = z0 * z0 + z1 * z1 + z2 * z2 + z3 * z3;
        const float ll = cst - 0.5f * s1 + s2 + 0.5f * q2;

        const float nm = fmaxf(mx, ll);
        sum = sum * __expf(mx - nm) + __expf(ll - nm);
        mx = nm;
    }

    if (row < N) out[row] = mx + logf(sum);
}

// ---------------------------------------------------------------------------
extern "C" void kernel_launch(void* const* d_in, const int* in_sizes, int n_in,
                              void* d_out, int out_size)
{
    const float* x  = (const float*)d_in[0];
    const float* MU = (const float*)d_in[1];
    const float* A  = (const float*)d_in[2];
    const float* Dm = (const float*)d_in[3];
    const float* PI = (const float*)d_in[4];
    float* out = (float*)d_out;

    const int N = in_sizes[0] / DDIM;

    const size_t smem = (size_t)DDIM * XSTRIDE * sizeof(float)
                      + (size_t)KCOMP * DDIM * sizeof(float4)
                      + (size_t)KCOMP * DDIM * sizeof(float2)
                      + (size_t)KCOMP * 5 * sizeof(float);

    cudaFuncSetAttribute(mfa_main, cudaFuncAttributeMaxDynamicSharedMemorySize,
                         (int)smem);

    mfa_precompute<<<KCOMP, DDIM>>>(MU, A, Dm, PI);

    const int grid = (N + TILE - 1) / TILE;
    mfa_main<<<grid, TPB, smem>>>(x, out, N);
}

// round 2
// speedup vs baseline: 1.3557x; 1.3557x over previous
#include <cuda_runtime.h>
#include <math.h>
#include <float.h>

#define KCOMP 32
#define DDIM  128
#define LDIM  4
#define TILE  128
#define TPB   128
#define XSTR  129            // pad: conflict-free reads, 4-way on one-time writes
#define NPAD  524288         // >= N, row stride for partial buffer

typedef unsigned long long u64;

// ---- device globals (no allocation allowed) -------------------------------
// Paired weight layout: [khalf][kpair(8)][d(128)][12 floats]
//   [0..1]=iD(a,b) [2..3]=v(a,b) [4..5]=Bp0 [6..7]=Bp1 [8..9]=Bp2 [10..11]=Bp3
__device__ float  g_Wp[2 * 8 * DDIM * 12];
__device__ float  g_cst[KCOMP];
__device__ float4 g_bm[KCOMP];
__device__ float  g_part[2 * NPAD];

// ---- f32x2 helpers --------------------------------------------------------
__device__ __forceinline__ u64 pack2(float v) {
    u64 r; unsigned u = __float_as_uint(v);
    asm("mov.b64 %0, {%1, %1};" : "=l"(r) : "r"(u));
    return r;
}
__device__ __forceinline__ void fma2(u64& d, u64 a, u64 b) {
    asm("fma.rn.f32x2 %0, %1, %2, %0;" : "+l"(d) : "l"(a), "l"(b));
}
__device__ __forceinline__ u64 mul2(u64 a, u64 b) {
    u64 d; asm("mul.rn.f32x2 %0, %1, %2;" : "=l"(d) : "l"(a), "l"(b));
    return d;
}
__device__ __forceinline__ float2 unpk(u64 a) {
    unsigned lo, hi;
    asm("mov.b64 {%0, %1}, %2;" : "=r"(lo), "=r"(hi) : "l"(a));
    float2 f; f.x = __uint_as_float(lo); f.y = __uint_as_float(hi);
    return f;
}

// ---------------------------------------------------------------------------
// Stage A: per-component precompute. One block per component, 128 threads.
// ---------------------------------------------------------------------------
__global__ void mfa_precompute(const float* __restrict__ MU,
                               const float* __restrict__ A,
                               const float* __restrict__ Dm,
                               const float* __restrict__ PI)
{
    const int k = blockIdx.x;
    const int d = threadIdx.x;

    __shared__ float  red[22][DDIM];
    __shared__ double rsum[22];
    __shared__ double sU[LDIM][LDIM];

    const float Dv = Dm[k * DDIM + d];
    const float iD = 1.0f / (Dv * Dv);
    const float mu = MU[k * DDIM + d];

    float a[LDIM], B[LDIM];
#pragma unroll
    for (int l = 0; l < LDIM; l++) {
        a[l] = A[(k * DDIM + d) * LDIM + l];
        B[l] = iD * a[l];
    }

    int idx = 0;
#pragma unroll
    for (int l = 0; l < LDIM; l++)
#pragma unroll
        for (int m = 0; m < LDIM; m++)
            red[idx++][d] = a[l] * B[m];
#pragma unroll
    for (int m = 0; m < LDIM; m++)
        red[idx++][d] = mu * B[m];
    red[idx++][d] = iD * mu * mu;
    red[idx++][d] = 2.0f * logf(Dv);
    __syncthreads();

    if (d < 22) {
        double s = 0.0;
        for (int i = 0; i < DDIM; i++) s += (double)red[d][i];
        rsum[d] = s;
    }
    __syncthreads();

    if (d == 0) {
        double Lm[LDIM][LDIM];
        for (int l = 0; l < LDIM; l++)
            for (int m = 0; m < LDIM; m++)
                Lm[l][m] = rsum[l * LDIM + m] + (l == m ? 1.0 : 0.0);
        double bmu[LDIM];
        for (int m = 0; m < LDIM; m++) bmu[m] = rsum[16 + m];
        const double tc  = rsum[20];
        const double sld = rsum[21];

        double G[LDIM][LDIM] = {};
        for (int i = 0; i < LDIM; i++) {
            for (int j = 0; j <= i; j++) {
                double s = Lm[i][j];
                for (int p = 0; p < j; p++) s -= G[i][p] * G[j][p];
                if (i == j) G[i][i] = sqrt(s);
                else        G[i][j] = s / G[j][j];
            }
        }
        double logdetL = 0.0;
        for (int i = 0; i < LDIM; i++) logdetL += 2.0 * log(G[i][i]);

        double U[LDIM][LDIM] = {};
        for (int j = 0; j < LDIM; j++) {
            U[j][j] = 1.0 / G[j][j];
            for (int i = j + 1; i < LDIM; i++) {
                double s = 0.0;
                for (int p = j; p < i; p++) s += G[i][p] * U[p][j];
                U[i][j] = -s / G[i][i];
            }
        }
        for (int l = 0; l < LDIM; l++)
            for (int m = 0; m < LDIM; m++)
                sU[l][m] = U[l][m];

        const double LOG2PI = 1.8378770664093454835606594728112;
        g_cst[k] = (float)((double)PI[k]
                  - 0.5 * ((double)DDIM * LOG2PI + logdetL + sld + tc));

        double bp[LDIM];
        for (int l = 0; l < LDIM; l++) {
            double s = 0.0;
            for (int m = 0; m <= l; m++) s += U[l][m] * bmu[m];
            bp[l] = s;
        }
        g_bm[k] = make_float4((float)bp[0], (float)bp[1], (float)bp[2], (float)bp[3]);
    }
    __syncthreads();

    float Bp[LDIM];
#pragma unroll
    for (int l = 0; l < LDIM; l++) {
        double s = 0.0;
        for (int m = 0; m <= l; m++) s += sU[l][m] * (double)B[m];
        Bp[l] = (float)s;
    }

    // Paired layout write
    const int khalf = k >> 4;
    const int kp    = (k & 15) >> 1;
    const int b     = k & 1;
    float* wp = g_Wp + (((khalf * 8 + kp) * DDIM) + d) * 12;
    wp[0  + b] = iD;
    wp[2  + b] = iD * mu;
    wp[4  + b] = Bp[0];
    wp[6  + b] = Bp[1];
    wp[8  + b] = Bp[2];
    wp[10 + b] = Bp[3];
}

// ---------------------------------------------------------------------------
// Stage B: main kernel. blockIdx.y selects which 16 components this CTA does.
// f32x2: each FMA lane-pair processes two components for the same row.
// ---------------------------------------------------------------------------
__global__ void __launch_bounds__(TPB, 2)
mfa_main(const float* __restrict__ x, int N)
{
    extern __shared__ float smem[];
    float4* sW = (float4*)smem;                 // 8*128*3 = 3072 float4 (49152B)
    float*  xs = smem + 8 * DDIM * 12;          // DDIM * XSTR floats   (66048B)
    float*  sC = xs + DDIM * XSTR;              // 16*5 floats

    const int tid  = threadIdx.x;
    const int row0 = blockIdx.x * TILE;
    const int kh   = blockIdx.y;

    // Load this half's weights into shared
    {
        const float4* gW = ((const float4*)g_Wp) + kh * 3072;
        for (int i = tid; i < 3072; i += TPB) sW[i] = gW[i];
        if (tid < 16) {
            const int k = kh * 16 + tid;
            sC[tid * 5 + 0] = g_cst[k];
            float4 b = g_bm[k];
            sC[tid * 5 + 1] = b.x; sC[tid * 5 + 2] = b.y;
            sC[tid * 5 + 3] = b.z; sC[tid * 5 + 4] = b.w;
        }
    }

    // Load x tile transposed: xs[d][r]
    {
        const int NQ = TILE * (DDIM / 4);
        for (int i = tid; i < NQ; i += TPB) {
            const int r = i >> 5;
            const int q = i & 31;
            const int row = row0 + r;
            float4 v = (row < N)
                ? __ldg((const float4*)x + (size_t)row * (DDIM / 4) + q)
                : make_float4(0.f, 0.f, 0.f, 0.f);
            const int base = (q * 4) * XSTR + r;
            xs[base + 0 * XSTR] = v.x;
            xs[base + 1 * XSTR] = v.y;
            xs[base + 2 * XSTR] = v.z;
            xs[base + 3 * XSTR] = v.w;
        }
    }
    __syncthreads();

    float mx = -FLT_MAX, sum = 0.f;

#pragma unroll
    for (int i = 0; i < 4; i++) {
        const float4* wA = sW + (2 * i + 0) * (DDIM * 3);
        const float4* wB = sW + (2 * i + 1) * (DDIM * 3);

        u64 S1a = 0, S2a = 0, Z0a = 0, Z1a = 0, Z2a = 0, Z3a = 0;
        u64 S1b = 0, S2b = 0, Z0b = 0, Z1b = 0, Z2b = 0, Z3b = 0;

#pragma unroll 4
        for (int d = 0; d < DDIM; d++) {
            const float xv  = xs[d * XSTR + tid];
            const u64   xp  = pack2(xv);
            const u64   x2p = mul2(xp, xp);

            const ulonglong2* pa = (const ulonglong2*)(wA + d * 3);
            const ulonglong2* pb = (const ulonglong2*)(wB + d * 3);
            const ulonglong2 a0 = pa[0], a1 = pa[1], a2 = pa[2];
            const ulonglong2 b0 = pb[0], b1 = pb[1], b2 = pb[2];

            fma2(S1a, a0.x, x2p); fma2(S2a, a0.y, xp);
            fma2(Z0a, a1.x, xp);  fma2(Z1a, a1.y, xp);
            fma2(Z2a, a2.x, xp);  fma2(Z3a, a2.y, xp);
            fma2(S1b, b0.x, x2p); fma2(S2b, b0.y, xp);
            fma2(Z0b, b1.x, xp);  fma2(Z1b, b1.y, xp);
            fma2(Z2b, b2.x, xp);  fma2(Z3b, b2.y, xp);
        }

        // Epilogue: 4 components (2 per accumulator set)
#pragma unroll
        for (int half = 0; half < 2; half++) {
            const float2 s1 = unpk(half ? S1b : S1a);
            const float2 s2 = unpk(half ? S2b : S2a);
            const float2 z0 = unpk(half ? Z0b : Z0a);
            const float2 z1 = unpk(half ? Z1b : Z1a);
            const float2 z2 = unpk(half ? Z2b : Z2a);
            const float2 z3 = unpk(half ? Z3b : Z3a);
            const int kbase = (2 * i + half) * 2;   // local component index
#pragma unroll
            for (int b = 0; b < 2; b++) {
                const float* cc = sC + (kbase + b) * 5;
                const float u0 = (b ? z0.y : z0.x) - cc[1];
                const float u1 = (b ? z1.y : z1.x) - cc[2];
                const float u2 = (b ? z2.y : z2.x) - cc[3];
                const float u3 = (b ? z3.y : z3.x) - cc[4];
                const float q2 = u0 * u0 + u1 * u1 + u2 * u2 + u3 * u3;
                const float ll = cc[0] - 0.5f * (b ? s1.y : s1.x)
                               + (b ? s2.y : s2.x) + 0.5f * q2;
                const float nm = fmaxf(mx, ll);
                sum = sum * __expf(mx - nm) + __expf(ll - nm);
                mx = nm;
            }
        }
    }

    const int row = row0 + tid;
    if (row < N) g_part[kh * NPAD + row] = mx + logf(sum);
}

// ---------------------------------------------------------------------------
// Stage C: combine the two partial logsumexps.
// ---------------------------------------------------------------------------
__global__ void mfa_combine(float* __restrict__ out, int N)
{
    const int i = blockIdx.x * 256 + threadIdx.x;
    if (i < N) {
        const float a = g_part[i];
        const float b = g_part[NPAD + i];
        const float m = fmaxf(a, b);
        out[i] = m + logf(__expf(a - m) + __expf(b - m));
    }
}

// ---------------------------------------------------------------------------
extern "C" void kernel_launch(void* const* d_in, const int* in_sizes, int n_in,
                              void* d_out, int out_size)
{
    const float* x  = (const float*)d_in[0];
    const float* MU = (const float*)d_in[1];
    const float* A  = (const float*)d_in[2];
    const float* Dm = (const float*)d_in[3];
    const float* PI = (const float*)d_in[4];
    float* out = (float*)d_out;

    const int N = in_sizes[0] / DDIM;

    const size_t smem = (size_t)(8 * DDIM * 12 + DDIM * XSTR + 16 * 5) * sizeof(float);
    cudaFuncSetAttribute(mfa_main, cudaFuncAttributeMaxDynamicSharedMemorySize,
                         (int)smem);

    mfa_precompute<<<KCOMP, DDIM>>>(MU, A, Dm, PI);

    dim3 grid((N + TILE - 1) / TILE, 2);
    mfa_main<<<grid, TPB, smem>>>(x, N);

    mfa_combine<<<(N + 255) / 256, 256>>>(out, N);
}

// round 4
// speedup vs baseline: 8.7630x; 6.4640x over previous
#include <cuda_runtime.h>
#include <math.h>
#include <float.h>
#include <stdint.h>
#include <cuda_fp16.h>

#define KCOMP 32
#define DDIM  128
#define LDIM  4
#define TPB   128
#define ROWS_TILE 128

// smem byte offsets
#define SM_X   0        // x tile:  128 rows x 256B (fp16)
#define SM_X2  32768    // x^2 tile
#define SM_W   65536    // weights: 192 rows x 256B (fp16)
#define SM_C   114688   // cst[32] + bm[4][32] floats
#define SMEM_TOTAL (114688 + 640)

// ---- device globals -------------------------------------------------------
__device__ uint4  g_Wh[192 * 16];      // fp16 weights, row n: 128 halves
__device__ float  g_cst[KCOMP];
__device__ float4 g_bm[KCOMP];

// ---- helpers --------------------------------------------------------------
__device__ __forceinline__ uint32_t h2pack(float a, float b) {
    __half2 h = __floats2half2_rn(a, b);
    return *(uint32_t*)&h;
}

__device__ __forceinline__ void mma16816(float c[4], const uint32_t a[4],
                                         uint32_t b0, uint32_t b1) {
    asm volatile(
        "mma.sync.aligned.m16n8k16.row.col.f32.f16.f16.f32 "
        "{%0,%1,%2,%3}, {%4,%5,%6,%7}, {%8,%9}, {%0,%1,%2,%3};"
        : "+f"(c[0]), "+f"(c[1]), "+f"(c[2]), "+f"(c[3])
        : "r"(a[0]), "r"(a[1]), "r"(a[2]), "r"(a[3]), "r"(b0), "r"(b1));
}

// ---------------------------------------------------------------------------
// Stage A: per-component precompute (verified R1-R2 math; fp16 weight output).
// ---------------------------------------------------------------------------
__global__ void mfa_precompute(const float* __restrict__ MU,
                               const float* __restrict__ A,
                               const float* __restrict__ Dm,
                               const float* __restrict__ PI)
{
    const int k = blockIdx.x;
    const int d = threadIdx.x;

    __shared__ float  red[22][DDIM];
    __shared__ double rsum[22];
    __shared__ double sU[LDIM][LDIM];

    const float Dv = Dm[k * DDIM + d];
    const float iD = 1.0f / (Dv * Dv);
    const float mu = MU[k * DDIM + d];

    float a[LDIM], B[LDIM];
#pragma unroll
    for (int l = 0; l < LDIM; l++) {
        a[l] = A[(k * DDIM + d) * LDIM + l];
        B[l] = iD * a[l];
    }

    int idx = 0;
#pragma unroll
    for (int l = 0; l < LDIM; l++)
#pragma unroll
        for (int m = 0; m < LDIM; m++)
            red[idx++][d] = a[l] * B[m];
#pragma unroll
    for (int m = 0; m < LDIM; m++)
        red[idx++][d] = mu * B[m];
    red[idx++][d] = iD * mu * mu;
    red[idx++][d] = 2.0f * logf(Dv);
    __syncthreads();

    if (d < 22) {
        double s = 0.0;
        for (int i = 0; i < DDIM; i++) s += (double)red[d][i];
        rsum[d] = s;
    }
    __syncthreads();

    if (d == 0) {
        double Lm[LDIM][LDIM];
        for (int l = 0; l < LDIM; l++)
            for (int m = 0; m < LDIM; m++)
                Lm[l][m] = rsum[l * LDIM + m] + (l == m ? 1.0 : 0.0);
        double bmu[LDIM];
        for (int m = 0; m < LDIM; m++) bmu[m] = rsum[16 + m];
        const double tc  = rsum[20];
        const double sld = rsum[21];

        double G[LDIM][LDIM] = {};
        for (int i = 0; i < LDIM; i++) {
            for (int j = 0; j <= i; j++) {
                double s = Lm[i][j];
                for (int p = 0; p < j; p++) s -= G[i][p] * G[j][p];
                if (i == j) G[i][i] = sqrt(s);
                else        G[i][j] = s / G[j][j];
            }
        }
        double logdetL = 0.0;
        for (int i = 0; i < LDIM; i++) logdetL += 2.0 * log(G[i][i]);

        double U[LDIM][LDIM] = {};
        for (int j = 0; j < LDIM; j++) {
            U[j][j] = 1.0 / G[j][j];
            for (int i = j + 1; i < LDIM; i++) {
                double s = 0.0;
                for (int p = j; p < i; p++) s += G[i][p] * U[p][j];
                U[i][j] = -s / G[i][i];
            }
        }
        for (int l = 0; l < LDIM; l++)
            for (int m = 0; m < LDIM; m++)
                sU[l][m] = U[l][m];

        const double LOG2PI = 1.8378770664093454835606594728112;
        g_cst[k] = (float)((double)PI[k]
                  - 0.5 * ((double)DDIM * LOG2PI + logdetL + sld + tc));

        double bp[LDIM];
        for (int l = 0; l < LDIM; l++) {
            double s = 0.0;
            for (int m = 0; m <= l; m++) s += U[l][m] * bmu[m];
            bp[l] = s;
        }
        g_bm[k] = make_float4((float)bp[0], (float)bp[1], (float)bp[2], (float)bp[3]);
    }
    __syncthreads();

    float Bp[LDIM];
#pragma unroll
    for (int l = 0; l < LDIM; l++) {
        double s = 0.0;
        for (int m = 0; m <= l; m++) s += sU[l][m] * (double)B[m];
        Bp[l] = (float)s;
    }

    __half* Wh = (__half*)g_Wh;
    Wh[(size_t)k * DDIM + d] = __float2half_rn(iD * mu);            // s2 rows 0..31
#pragma unroll
    for (int j = 0; j < LDIM; j++)                                   // z rows 32..159
        Wh[(size_t)(32 + 32 * j + k) * DDIM + d] = __float2half_rn(Bp[j]);
    Wh[(size_t)(160 + k) * DDIM + d] = __float2half_rn(iD);          // s1 rows 160..191
}

// ---------------------------------------------------------------------------
// Stage B: persistent mma.sync kernel. 4 warps x 32 rows = 128-row tiles.
// ---------------------------------------------------------------------------
__global__ void __launch_bounds__(TPB, 2)
mfa_mma(const float* __restrict__ x, float* __restrict__ out, int N, int ntiles)
{
    extern __shared__ char sm[];
    const int tid  = threadIdx.x;
    const int lane = tid & 31;
    const int w    = tid >> 5;
    const int qr   = lane >> 2;     // 0..7
    const int qc   = lane & 3;      // 0..3
    const uint32_t xorv = (uint32_t)qr << 4;

    // ---- load weights to smem once (persistent) ---------------------------
    for (int i = tid; i < 192 * 16; i += TPB) {
        const int r = i >> 4, s = i & 15;
        uint4 v = g_Wh[i];
        *(uint4*)(sm + SM_W + r * 256 + ((s ^ (r & 7)) << 4)) = v;
    }
    {
        float* c = (float*)(sm + SM_C);
        if (tid < 32) {
            c[tid] = g_cst[tid];
            float4 b = g_bm[tid];
            c[32 + tid] = b.x; c[64 + tid] = b.y;
            c[96 + tid] = b.z; c[128 + tid] = b.w;
        }
    }
    __syncthreads();

    const float* cst = (const float*)(sm + SM_C);
    const int rw = w * 32 + qr;     // warp row base + quad row

    for (int tile = blockIdx.x; tile < ntiles; tile += gridDim.x) {
        const int row0 = tile * ROWS_TILE;

        // ---- load x tile (fp16) + x^2 tile --------------------------------
        for (int i = tid; i < ROWS_TILE * 16; i += TPB) {
            const int r = i >> 4, s = i & 15;
            const int row = row0 + r;
            float4 v0, v1;
            if (row < N) {
                const float4* p = (const float4*)x + (size_t)row * 32 + s * 2;
                v0 = __ldg(p); v1 = __ldg(p + 1);
            } else {
                v0 = make_float4(0.f, 0.f, 0.f, 0.f); v1 = v0;
            }
            uint4 hx, hq;
            hx.x = h2pack(v0.x, v0.y); hx.y = h2pack(v0.z, v0.w);
            hx.z = h2pack(v1.x, v1.y); hx.w = h2pack(v1.z, v1.w);
            hq.x = h2pack(v0.x * v0.x, v0.y * v0.y);
            hq.y = h2pack(v0.z * v0.z, v0.w * v0.w);
            hq.z = h2pack(v1.x * v1.x, v1.y * v1.y);
            hq.w = h2pack(v1.z * v1.z, v1.w * v1.w);
            const uint32_t off = r * 256 + ((s ^ (r & 7)) << 4);
            *(uint4*)(sm + SM_X  + off) = hx;
            *(uint4*)(sm + SM_X2 + off) = hq;
        }
        __syncthreads();

        // ---- GEMM: acc[mt][nt][4] ----------------------------------------
        float acc[2][24][4];
#pragma unroll
        for (int mt = 0; mt < 2; mt++)
#pragma unroll
            for (int nt = 0; nt < 24; nt++)
#pragma unroll
                for (int e = 0; e < 4; e++) acc[mt][nt][e] = 0.f;

        const char* ax0 = sm + SM_X  + (size_t)rw * 256;
        const char* ax2 = sm + SM_X2 + (size_t)rw * 256;
        const char* wb  = sm + SM_W  + (size_t)qr * 256;

#pragma unroll
        for (int ch = 0; ch < 8; ch++) {
            const uint32_t c0 = ((uint32_t)(ch * 32 + qc * 4)) ^ xorv;
            const uint32_t c1 = c0 ^ 16u;

            uint32_t a0[4], a1[4];
            a0[0] = *(const uint32_t*)(ax0 + 0    * 256 + c0);
            a0[1] = *(const uint32_t*)(ax0 + 8    * 256 + c0);
            a0[2] = *(const uint32_t*)(ax0 + 0    * 256 + c1);
            a0[3] = *(const uint32_t*)(ax0 + 8    * 256 + c1);
            a1[0] = *(const uint32_t*)(ax0 + 16   * 256 + c0);
            a1[1] = *(const uint32_t*)(ax0 + 24   * 256 + c0);
            a1[2] = *(const uint32_t*)(ax0 + 16   * 256 + c1);
            a1[3] = *(const uint32_t*)(ax0 + 24   * 256 + c1);

#pragma unroll
            for (int nt = 0; nt < 20; nt++) {
                const uint32_t b0 = *(const uint32_t*)(wb + nt * 2048 + c0);
                const uint32_t b1 = *(const uint32_t*)(wb + nt * 2048 + c1);
                mma16816(acc[0][nt], a0, b0, b1);
                mma16816(acc[1][nt], a1, b0, b1);
            }

            uint32_t s0[4], s1v[4];
            s0[0]  = *(const uint32_t*)(ax2 + 0    * 256 + c0);
            s0[1]  = *(const uint32_t*)(ax2 + 8    * 256 + c0);
            s0[2]  = *(const uint32_t*)(ax2 + 0    * 256 + c1);
            s0[3]  = *(const uint32_t*)(ax2 + 8    * 256 + c1);
            s1v[0] = *(const uint32_t*)(ax2 + 16   * 256 + c0);
            s1v[1] = *(const uint32_t*)(ax2 + 24   * 256 + c0);
            s1v[2] = *(const uint32_t*)(ax2 + 16   * 256 + c1);
            s1v[3] = *(const uint32_t*)(ax2 + 24   * 256 + c1);

#pragma unroll
            for (int nt = 20; nt < 24; nt++) {
                const uint32_t b0 = *(const uint32_t*)(wb + nt * 2048 + c0);
                const uint32_t b1 = *(const uint32_t*)(wb + nt * 2048 + c1);
                mma16816(acc[0][nt], s0,  b0, b1);
                mma16816(acc[1][nt], s1v, b0, b1);
            }
        }

        // ---- epilogue: 8 comps/thread/row, butterfly over qc --------------
#pragma unroll
        for (int mt = 0; mt < 2; mt++) {
#pragma unroll
            for (int h = 0; h < 2; h++) {
                float ll[8];
#pragma unroll
                for (int j = 0; j < 4; j++) {
#pragma unroll
                    for (int p = 0; p < 2; p++) {
                        const int k = 8 * j + 2 * qc + p;
                        float v = cst[k] + acc[mt][j][2 * h + p]
                                - 0.5f * acc[mt][20 + j][2 * h + p];
#pragma unroll
                        for (int jj = 0; jj < 4; jj++) {
                            const float z = acc[mt][4 + 4 * jj + j][2 * h + p]
                                          - cst[32 + 32 * jj + k];
                            v = fmaf(0.5f * z, z, v);
                        }
                        ll[2 * j + p] = v;
                    }
                }
                float mx = ll[0];
#pragma unroll
                for (int i = 1; i < 8; i++) mx = fmaxf(mx, ll[i]);
                float sum = 0.f;
#pragma unroll
                for (int i = 0; i < 8; i++) sum += __expf(ll[i] - mx);

#pragma unroll
                for (int off = 1; off <= 2; off <<= 1) {
                    const float m2 = __shfl_xor_sync(0xffffffffu, mx,  off);
                    const float s2 = __shfl_xor_sync(0xffffffffu, sum, off);
                    const float nm = fmaxf(mx, m2);
                    sum = sum * __expf(mx - nm) + s2 * __expf(m2 - nm);
                    mx = nm;
                }

                const int row = row0 + w * 32 + mt * 16 + qr + 8 * h;
                if (qc == 0 && row < N) out[row] = mx + logf(sum);
            }
        }
        __syncthreads();
    }
}

// ---------------------------------------------------------------------------
extern "C" void kernel_launch(void* const* d_in, const int* in_sizes, int n_in,
                              void* d_out, int out_size)
{
    const float* x  = (const float*)d_in[0];
    const float* MU = (const float*)d_in[1];
    const float* A  = (const float*)d_in[2];
    const float* Dm = (const float*)d_in[3];
    const float* PI = (const float*)d_in[4];
    float* out = (float*)d_out;

    const int N = in_sizes[0] / DDIM;
    const int ntiles = (N + ROWS_TILE - 1) / ROWS_TILE;

    int nsm = 148;
    cudaDeviceGetAttribute(&nsm, cudaDevAttrMultiProcessorCount, 0);
    if (nsm <= 0) nsm = 148;
    int grid = 2 * nsm;
    if (grid > ntiles) grid = ntiles;

    cudaFuncSetAttribute(mfa_mma, cudaFuncAttributeMaxDynamicSharedMemorySize,
                         SMEM_TOTAL);

    mfa_precompute<<<KCOMP, DDIM>>>(MU, A, Dm, PI);
    mfa_mma<<<grid, TPB, SMEM_TOTAL>>>(x, out, N, ntiles);
}

// round 5
// speedup vs baseline: 8.8516x; 1.0101x over previous
#include <cuda_runtime.h>
#include <math.h>
#include <float.h>
#include <stdint.h>
#include <cuda_fp16.h>

#define KCOMP 32
#define DDIM  128
#define LDIM  4
#define TPB   128
#define ROWS_TILE 128

// smem byte offsets
#define SM_X   0        // x tile:  128 rows x 256B (fp16)
#define SM_X2  32768    // x^2 tile
#define SM_W   65536    // weights: 192 rows x 256B (fp16)
#define SM_C   114688   // cst[32] + bm[4][32] floats
#define SMEM_TOTAL (114688 + 640)

// ---- device globals -------------------------------------------------------
__device__ uint4  g_Wh[192 * 16];      // fp16 weights, row n: 128 halves
__device__ float  g_cst[KCOMP];
__device__ float4 g_bm[KCOMP];

// ---- helpers --------------------------------------------------------------
__device__ __forceinline__ uint32_t h2pack(float a, float b) {
    __half2 h = __floats2half2_rn(a, b);
    return *(uint32_t*)&h;
}
__device__ __forceinline__ uint32_t smem_u32(const void* p) {
    uint32_t a;
    asm("{ .reg .u64 t; cvta.to.shared.u64 t, %1; cvt.u32.u64 %0, t; }" : "=r"(a) : "l"(p));
    return a;
}
__device__ __forceinline__ void mma16816(float c[4], const uint32_t a[4],
                                         uint32_t b0, uint32_t b1) {
    asm volatile(
        "mma.sync.aligned.m16n8k16.row.col.f32.f16.f16.f32 "
        "{%0,%1,%2,%3}, {%4,%5,%6,%7}, {%8,%9}, {%0,%1,%2,%3};"
        : "+f"(c[0]), "+f"(c[1]), "+f"(c[2]), "+f"(c[3])
        : "r"(a[0]), "r"(a[1]), "r"(a[2]), "r"(a[3]), "r"(b0), "r"(b1));
}
__device__ __forceinline__ void ldsm4(uint32_t r[4], uint32_t addr) {
    asm volatile("ldmatrix.sync.aligned.m8n8.x4.shared.b16 {%0,%1,%2,%3}, [%4];"
        : "=r"(r[0]), "=r"(r[1]), "=r"(r[2]), "=r"(r[3]) : "r"(addr));
}

// ---------------------------------------------------------------------------
// Stage A: per-component precompute. 32 blocks x 1 warp; warp = component.
// Shuffle reductions in double; redundant per-lane 4x4 Cholesky (no smem).
// ---------------------------------------------------------------------------
__global__ void mfa_precompute(const float* __restrict__ MU,
                               const float* __restrict__ A,
                               const float* __restrict__ Dm,
                               const float* __restrict__ PI)
{
    const int k    = blockIdx.x;
    const int lane = threadIdx.x;

    double s[22];
#pragma unroll
    for (int j = 0; j < 22; j++) s[j] = 0.0;

#pragma unroll
    for (int i = 0; i < 4; i++) {
        const int d = lane + 32 * i;
        const float Dv = Dm[k * DDIM + d];
        const float iD = 1.0f / (Dv * Dv);
        const float mu = MU[k * DDIM + d];
        float a[LDIM], B[LDIM];
#pragma unroll
        for (int l = 0; l < LDIM; l++) {
            a[l] = A[(k * DDIM + d) * LDIM + l];
            B[l] = iD * a[l];
        }
        int idx = 0;
#pragma unroll
        for (int l = 0; l < LDIM; l++)
#pragma unroll
            for (int m = 0; m < LDIM; m++)
                s[idx++] += (double)(a[l] * B[m]);
#pragma unroll
        for (int m = 0; m < LDIM; m++)
            s[idx++] += (double)(mu * B[m]);
        s[20] += (double)(iD * mu * mu);
        s[21] += (double)(2.0f * logf(Dv));
    }

    // warp allreduce (all lanes end with totals)
#pragma unroll
    for (int j = 0; j < 22; j++)
#pragma unroll
        for (int o = 16; o; o >>= 1)
            s[j] += __shfl_xor_sync(0xffffffffu, s[j], o);

    // All lanes redundantly compute the 4x4 factorization (no divergence)
    double Lm[LDIM][LDIM], bmu[LDIM];
#pragma unroll
    for (int l = 0; l < LDIM; l++)
#pragma unroll
        for (int m = 0; m < LDIM; m++)
            Lm[l][m] = s[l * LDIM + m] + (l == m ? 1.0 : 0.0);
#pragma unroll
    for (int m = 0; m < LDIM; m++) bmu[m] = s[16 + m];
    const double tc  = s[20];
    const double sld = s[21];

    double G[LDIM][LDIM] = {};
#pragma unroll
    for (int i = 0; i < LDIM; i++) {
#pragma unroll
        for (int j = 0; j <= i; j++) {
            double v = Lm[i][j];
#pragma unroll
            for (int p = 0; p < LDIM; p++)
                if (p < j) v -= G[i][p] * G[j][p];
            if (i == j) G[i][i] = sqrt(v);
            else        G[i][j] = v / G[j][j];
        }
    }
    double logdetL = 0.0;
#pragma unroll
    for (int i = 0; i < LDIM; i++) logdetL += 2.0 * log(G[i][i]);

    double U[LDIM][LDIM] = {};
#pragma unroll
    for (int j = 0; j < LDIM; j++) {
        U[j][j] = 1.0 / G[j][j];
#pragma unroll
        for (int i = 0; i < LDIM; i++) {
            if (i > j) {
                double v = 0.0;
#pragma unroll
                for (int p = 0; p < LDIM; p++)
                    if (p >= j && p < i) v += G[i][p] * U[p][j];
                U[i][j] = -v / G[i][i];
            }
        }
    }

    const double LOG2PI = 1.8378770664093454835606594728112;
    if (lane == 0) {
        g_cst[k] = (float)((double)PI[k]
                  - 0.5 * ((double)DDIM * LOG2PI + logdetL + sld + tc));
        double bp[LDIM];
#pragma unroll
        for (int l = 0; l < LDIM; l++) {
            double v = 0.0;
#pragma unroll
            for (int m = 0; m <= l; m++) v += U[l][m] * bmu[m];
            bp[l] = v;
        }
        g_bm[k] = make_float4((float)bp[0], (float)bp[1], (float)bp[2], (float)bp[3]);
    }

    // weight writes: each lane handles 4 d values
    __half* Wh = (__half*)g_Wh;
#pragma unroll
    for (int i = 0; i < 4; i++) {
        const int d = lane + 32 * i;
        const float Dv = Dm[k * DDIM + d];
        const float iD = 1.0f / (Dv * Dv);
        const float mu = MU[k * DDIM + d];
        float B[LDIM];
#pragma unroll
        for (int l = 0; l < LDIM; l++)
            B[l] = iD * A[(k * DDIM + d) * LDIM + l];
        float Bp[LDIM];
#pragma unroll
        for (int l = 0; l < LDIM; l++) {
            double v = 0.0;
#pragma unroll
            for (int m = 0; m <= l; m++) v += U[l][m] * (double)B[m];
            Bp[l] = (float)v;
        }
        Wh[(size_t)k * DDIM + d] = __float2half_rn(iD * mu);
#pragma unroll
        for (int j = 0; j < LDIM; j++)
            Wh[(size_t)(32 + 32 * j + k) * DDIM + d] = __float2half_rn(Bp[j]);
        Wh[(size_t)(160 + k) * DDIM + d] = __float2half_rn(iD);
    }
}

// ---------------------------------------------------------------------------
// Stage B: persistent mma.sync kernel with ldmatrix fragment loads.
// ---------------------------------------------------------------------------
__global__ void __launch_bounds__(TPB, 2)
mfa_mma(const float* __restrict__ x, float* __restrict__ out, int N, int ntiles)
{
    extern __shared__ char smc[];
    const int tid  = threadIdx.x;
    const int lane = tid & 31;
    const int w    = tid >> 5;
    const int qr   = lane >> 2;     // 0..7
    const int qc   = lane & 3;      // 0..3
    const int rin  = lane & 7;
    const int mat  = lane >> 3;     // 0..3

    const uint32_t sb = smem_u32(smc);

    // ---- load weights to smem once (persistent) ---------------------------
    for (int i = tid; i < 192 * 16; i += TPB) {
        const int r = i >> 4, s = i & 15;
        uint4 v = g_Wh[i];
        *(uint4*)(smc + SM_W + r * 256 + ((s ^ (r & 7)) << 4)) = v;
    }
    {
        float* c = (float*)(smc + SM_C);
        if (tid < 32) {
            c[tid] = g_cst[tid];
            float4 b = g_bm[tid];
            c[32 + tid] = b.x; c[64 + tid] = b.y;
            c[96 + tid] = b.z; c[128 + tid] = b.w;
        }
    }
    __syncthreads();

    const float* cst = (const float*)(smc + SM_C);

    // ldmatrix per-lane base addresses
    // A (x / x2), m-tile mt: row = w*32 + mt*16 + (mat&1)*8 + rin, gran = 2ch+(mat>>1)
    // B, nt-pair t: row = t*16 + (mat>>1)*8 + rin, gran = 2ch+(mat&1)
    uint32_t a_pre[2], a2_pre[2];
#pragma unroll
    for (int mt = 0; mt < 2; mt++) {
        const uint32_t row = (uint32_t)(w * 32 + mt * 16 + (mat & 1) * 8 + rin);
        a_pre[mt]  = sb + SM_X  + row * 256u;
        a2_pre[mt] = sb + SM_X2 + row * 256u;
    }
    const uint32_t b_pre = sb + SM_W + (uint32_t)((mat >> 1) * 8 + rin) * 256u;

    for (int tile = blockIdx.x; tile < ntiles; tile += gridDim.x) {
        const int row0 = tile * ROWS_TILE;

        // ---- load x tile (fp16) + x^2 tile --------------------------------
#pragma unroll 4
        for (int i = tid; i < ROWS_TILE * 16; i += TPB) {
            const int r = i >> 4, s = i & 15;
            const int row = row0 + r;
            float4 v0, v1;
            if (row < N) {
                const float4* p = (const float4*)x + (size_t)row * 32 + s * 2;
                v0 = __ldg(p); v1 = __ldg(p + 1);
            } else {
                v0 = make_float4(0.f, 0.f, 0.f, 0.f); v1 = v0;
            }
            uint4 hx, hq;
            hx.x = h2pack(v0.x, v0.y); hx.y = h2pack(v0.z, v0.w);
            hx.z = h2pack(v1.x, v1.y); hx.w = h2pack(v1.z, v1.w);
            hq.x = h2pack(v0.x * v0.x, v0.y * v0.y);
            hq.y = h2pack(v0.z * v0.z, v0.w * v0.w);
            hq.z = h2pack(v1.x * v1.x, v1.y * v1.y);
            hq.w = h2pack(v1.z * v1.z, v1.w * v1.w);
            const uint32_t off = r * 256 + ((s ^ (r & 7)) << 4);
            *(uint4*)(smc + SM_X  + off) = hx;
            *(uint4*)(smc + SM_X2 + off) = hq;
        }
        __syncthreads();

        // ---- GEMM ----------------------------------------------------------
        float acc[2][24][4];
#pragma unroll
        for (int mt = 0; mt < 2; mt++)
#pragma unroll
            for (int nt = 0; nt < 24; nt++)
#pragma unroll
                for (int e = 0; e < 4; e++) acc[mt][nt][e] = 0.f;

#pragma unroll
        for (int ch = 0; ch < 8; ch++) {
            const uint32_t xa = (((uint32_t)(ch * 2 + (mat >> 1))) ^ (uint32_t)rin) << 4;
            const uint32_t xb = (((uint32_t)(ch * 2 + (mat & 1)))  ^ (uint32_t)rin) << 4;

            uint32_t ax[2][4];
            ldsm4(ax[0], a_pre[0] + xa);
            ldsm4(ax[1], a_pre[1] + xa);

#pragma unroll
            for (int t = 0; t < 10; t++) {
                uint32_t b[4];
                ldsm4(b, b_pre + (uint32_t)t * 4096u + xb);
                mma16816(acc[0][2 * t],     ax[0], b[0], b[1]);
                mma16816(acc[1][2 * t],     ax[1], b[0], b[1]);
                mma16816(acc[0][2 * t + 1], ax[0], b[2], b[3]);
                mma16816(acc[1][2 * t + 1], ax[1], b[2], b[3]);
            }

            uint32_t aq[2][4];
            ldsm4(aq[0], a2_pre[0] + xa);
            ldsm4(aq[1], a2_pre[1] + xa);

#pragma unroll
            for (int t = 10; t < 12; t++) {
                uint32_t b[4];
                ldsm4(b, b_pre + (uint32_t)t * 4096u + xb);
                mma16816(acc[0][2 * t],     aq[0], b[0], b[1]);
                mma16816(acc[1][2 * t],     aq[1], b[0], b[1]);
                mma16816(acc[0][2 * t + 1], aq[0], b[2], b[3]);
                mma16816(acc[1][2 * t + 1], aq[1], b[2], b[3]);
            }
        }

        // ---- epilogue: 8 comps/thread/row, butterfly over qc --------------
#pragma unroll
        for (int mt = 0; mt < 2; mt++) {
#pragma unroll
            for (int h = 0; h < 2; h++) {
                float ll[8];
#pragma unroll
                for (int j = 0; j < 4; j++) {
#pragma unroll
                    for (int p = 0; p < 2; p++) {
                        const int k = 8 * j + 2 * qc + p;
                        float v = cst[k] + acc[mt][j][2 * h + p]
                                - 0.5f * acc[mt][20 + j][2 * h + p];
#pragma unroll
                        for (int jj = 0; jj < 4; jj++) {
                            const float z = acc[mt][4 + 4 * jj + j][2 * h + p]
                                          - cst[32 + 32 * jj + k];
                            v = fmaf(0.5f * z, z, v);
                        }
                        ll[2 * j + p] = v;
                    }
                }
                float mx = ll[0];
#pragma unroll
                for (int i = 1; i < 8; i++) mx = fmaxf(mx, ll[i]);
                float sum = 0.f;
#pragma unroll
                for (int i = 0; i < 8; i++) sum += __expf(ll[i] - mx);

#pragma unroll
                for (int off = 1; off <= 2; off <<= 1) {
                    const float m2 = __shfl_xor_sync(0xffffffffu, mx,  off);
                    const float s2 = __shfl_xor_sync(0xffffffffu, sum, off);
                    const float nm = fmaxf(mx, m2);
                    sum = sum * __expf(mx - nm) + s2 * __expf(m2 - nm);
                    mx = nm;
                }

                const int row = row0 + w * 32 + mt * 16 + qr + 8 * h;
                if (qc == 0 && row < N) out[row] = mx + logf(sum);
            }
        }
        __syncthreads();
    }
}

// ---------------------------------------------------------------------------
extern "C" void kernel_launch(void* const* d_in, const int* in_sizes, int n_in,
                              void* d_out, int out_size)
{
    const float* x  = (const float*)d_in[0];
    const float* MU = (const float*)d_in[1];
    const float* A  = (const float*)d_in[2];
    const float* Dm = (const float*)d_in[3];
    const float* PI = (const float*)d_in[4];
    float* out = (float*)d_out;

    const int N = in_sizes[0] / DDIM;
    const int ntiles = (N + ROWS_TILE - 1) / ROWS_TILE;

    int nsm = 148;
    cudaDeviceGetAttribute(&nsm, cudaDevAttrMultiProcessorCount, 0);
    if (nsm <= 0) nsm = 148;
    int grid = 2 * nsm;
    if (grid > ntiles) grid = ntiles;

    cudaFuncSetAttribute(mfa_mma, cudaFuncAttributeMaxDynamicSharedMemorySize,
                         SMEM_TOTAL);

    mfa_precompute<<<KCOMP, 32>>>(MU, A, Dm, PI);
    mfa_mma<<<grid, TPB, SMEM_TOTAL>>>(x, out, N, ntiles);
}

// round 6
// speedup vs baseline: 11.1233x; 1.2566x over previous
#include <cuda_runtime.h>
#include <math.h>
#include <float.h>
#include <stdint.h>
#include <cuda_fp16.h>

#define KCOMP 32
#define DDIM  128
#define LDIM  4
#define TPB   256
#define ROWS_TILE 128

// smem byte offsets (115328B total, proven 2-CTA/SM config)
#define SM_X   0        // x tile:  128 rows x 256B (fp16); first 2KB aliased as sP
#define SM_X2  32768    // x^2 tile
#define SM_W   65536    // weights: 192 rows x 256B (fp16)
#define SM_C   114688   // cst[32] + bm[4][32] floats
#define SMEM_TOTAL (114688 + 640)

// ---- device globals -------------------------------------------------------
__device__ uint4  g_Wh[192 * 16];      // fp16 weights, row n: 128 halves
__device__ float  g_cst[KCOMP];
__device__ float4 g_bm[KCOMP];

// ---- helpers --------------------------------------------------------------
__device__ __forceinline__ uint32_t h2pack(float a, float b) {
    __half2 h = __floats2half2_rn(a, b);
    return *(uint32_t*)&h;
}
__device__ __forceinline__ uint32_t smem_u32(const void* p) {
    uint32_t a;
    asm("{ .reg .u64 t; cvta.to.shared.u64 t, %1; cvt.u32.u64 %0, t; }" : "=r"(a) : "l"(p));
    return a;
}
__device__ __forceinline__ void mma16816(float c[4], const uint32_t a[4],
                                         uint32_t b0, uint32_t b1) {
    asm volatile(
        "mma.sync.aligned.m16n8k16.row.col.f32.f16.f16.f32 "
        "{%0,%1,%2,%3}, {%4,%5,%6,%7}, {%8,%9}, {%0,%1,%2,%3};"
        : "+f"(c[0]), "+f"(c[1]), "+f"(c[2]), "+f"(c[3])
        : "r"(a[0]), "r"(a[1]), "r"(a[2]), "r"(a[3]), "r"(b0), "r"(b1));
}
__device__ __forceinline__ void ldsm4(uint32_t r[4], uint32_t addr) {
    asm volatile("ldmatrix.sync.aligned.m8n8.x4.shared.b16 {%0,%1,%2,%3}, [%4];"
        : "=r"(r[0]), "=r"(r[1]), "=r"(r[2]), "=r"(r[3]) : "r"(addr));
}

// ---------------------------------------------------------------------------
// Stage A: per-component precompute. 32 blocks x 1 warp; fp32 throughout
// (L = I + A^T B is I-dominant, A ~ 0.1 scale => perfectly conditioned).
// ---------------------------------------------------------------------------
__global__ void mfa_precompute(const float* __restrict__ MU,
                               const float* __restrict__ A,
                               const float* __restrict__ Dm,
                               const float* __restrict__ PI)
{
    const int k    = blockIdx.x;
    const int lane = threadIdx.x;

    float s[22];
#pragma unroll
    for (int j = 0; j < 22; j++) s[j] = 0.f;

#pragma unroll
    for (int i = 0; i < 4; i++) {
        const int d = lane + 32 * i;
        const float Dv = Dm[k * DDIM + d];
        const float iD = 1.0f / (Dv * Dv);
        const float mu = MU[k * DDIM + d];
        float a[LDIM], B[LDIM];
#pragma unroll
        for (int l = 0; l < LDIM; l++) {
            a[l] = A[(k * DDIM + d) * LDIM + l];
            B[l] = iD * a[l];
        }
        int idx = 0;
#pragma unroll
        for (int l = 0; l < LDIM; l++)
#pragma unroll
            for (int m = 0; m < LDIM; m++)
                s[idx++] += a[l] * B[m];
#pragma unroll
        for (int m = 0; m < LDIM; m++)
            s[idx++] += mu * B[m];
        s[20] += iD * mu * mu;
        s[21] += 2.0f * logf(Dv);
    }

    // warp allreduce
#pragma unroll
    for (int j = 0; j < 22; j++)
#pragma unroll
        for (int o = 16; o; o >>= 1)
            s[j] += __shfl_xor_sync(0xffffffffu, s[j], o);

    // redundant per-lane 4x4 Cholesky (no divergence)
    float Lm[LDIM][LDIM], bmu[LDIM];
#pragma unroll
    for (int l = 0; l < LDIM; l++)
#pragma unroll
        for (int m = 0; m < LDIM; m++)
            Lm[l][m] = s[l * LDIM + m] + (l == m ? 1.0f : 0.0f);
#pragma unroll
    for (int m = 0; m < LDIM; m++) bmu[m] = s[16 + m];
    const float tc  = s[20];
    const float sld = s[21];

    float G[LDIM][LDIM] = {};
#pragma unroll
    for (int i = 0; i < LDIM; i++) {
#pragma unroll
        for (int j = 0; j <= i; j++) {
            float v = Lm[i][j];
#pragma unroll
            for (int p = 0; p < LDIM; p++)
                if (p < j) v -= G[i][p] * G[j][p];
            if (i == j) G[i][i] = sqrtf(v);
            else        G[i][j] = v / G[j][j];
        }
    }
    float logdetL = 0.f;
#pragma unroll
    for (int i = 0; i < LDIM; i++) logdetL += 2.0f * logf(G[i][i]);

    float U[LDIM][LDIM] = {};
#pragma unroll
    for (int j = 0; j < LDIM; j++) {
        U[j][j] = 1.0f / G[j][j];
#pragma unroll
        for (int i = 0; i < LDIM; i++) {
            if (i > j) {
                float v = 0.f;
#pragma unroll
                for (int p = 0; p < LDIM; p++)
                    if (p >= j && p < i) v += G[i][p] * U[p][j];
                U[i][j] = -v / G[i][i];
            }
        }
    }

    if (lane == 0) {
        const float LOG2PI = 1.8378770664093454835606594728112f;
        g_cst[k] = PI[k] - 0.5f * ((float)DDIM * LOG2PI + logdetL + sld + tc);
        float bp[LDIM];
#pragma unroll
        for (int l = 0; l < LDIM; l++) {
            float v = 0.f;
#pragma unroll
            for (int m = 0; m <= l; m++) v += U[l][m] * bmu[m];
            bp[l] = v;
        }
        g_bm[k] = make_float4(bp[0], bp[1], bp[2], bp[3]);
    }

    __half* Wh = (__half*)g_Wh;
#pragma unroll
    for (int i = 0; i < 4; i++) {
        const int d = lane + 32 * i;
        const float Dv = Dm[k * DDIM + d];
        const float iD = 1.0f / (Dv * Dv);
        const float mu = MU[k * DDIM + d];
        float B[LDIM];
#pragma unroll
        for (int l = 0; l < LDIM; l++)
            B[l] = iD * A[(k * DDIM + d) * LDIM + l];
        float Bp[LDIM];
#pragma unroll
        for (int l = 0; l < LDIM; l++) {
            float v = 0.f;
#pragma unroll
            for (int m = 0; m <= l; m++) v += U[l][m] * B[m];
            Bp[l] = v;
        }
        Wh[(size_t)k * DDIM + d] = __float2half_rn(iD * mu);
#pragma unroll
        for (int j = 0; j < LDIM; j++)
            Wh[(size_t)(32 + 32 * j + k) * DDIM + d] = __float2half_rn(Bp[j]);
        Wh[(size_t)(160 + k) * DDIM + d] = __float2half_rn(iD);
    }
}

// ---------------------------------------------------------------------------
// Stage B: persistent mma.sync kernel. 8 warps: (wm rows-32) x (wk comp-16).
// ---------------------------------------------------------------------------
__global__ void __launch_bounds__(TPB, 2)
mfa_mma(const float* __restrict__ x, float* __restrict__ out, int N, int ntiles)
{
    extern __shared__ char smc[];
    const int tid  = threadIdx.x;
    const int lane = tid & 31;
    const int w    = tid >> 5;
    const int wm   = w & 3;         // row group (32 rows)
    const int wk   = w >> 2;        // component half (16 comps)
    const int qr   = lane >> 2;     // 0..7
    const int qc   = lane & 3;      // 0..3
    const int rin  = lane & 7;
    const int mat  = lane >> 3;     // 0..3

    const uint32_t sb = smem_u32(smc);
    float2* sP = (float2*)(smc + SM_X);      // ALIAS of x-tile head (sync-fenced)

    // ---- load weights to smem once (persistent) ---------------------------
    for (int i = tid; i < 192 * 16; i += TPB) {
        const int r = i >> 4, s = i & 15;
        uint4 v = g_Wh[i];
        *(uint4*)(smc + SM_W + r * 256 + ((s ^ (r & 7)) << 4)) = v;
    }
    {
        float* c = (float*)(smc + SM_C);
        if (tid < 32) {
            c[tid] = g_cst[tid];
            float4 b = g_bm[tid];
            c[32 + tid] = b.x; c[64 + tid] = b.y;
            c[96 + tid] = b.z; c[128 + tid] = b.w;
        }
    }
    __syncthreads();

    const float* cst = (const float*)(smc + SM_C);

    uint32_t a_pre[2], a2_pre[2];
#pragma unroll
    for (int mt = 0; mt < 2; mt++) {
        const uint32_t row = (uint32_t)(wm * 32 + mt * 16 + (mat & 1) * 8 + rin);
        a_pre[mt]  = sb + SM_X  + row * 256u;
        a2_pre[mt] = sb + SM_X2 + row * 256u;
    }
    // B rows: g*32 + wk*16 + (mat>>1)*8 + rin  (g offset applied per group)
    const uint32_t b_pre = sb + SM_W
        + (uint32_t)(wk * 16 + (mat >> 1) * 8 + rin) * 256u;

    for (int tile = blockIdx.x; tile < ntiles; tile += gridDim.x) {
        const int row0 = tile * ROWS_TILE;

        // ---- load x tile (fp16) + x^2 tile --------------------------------
#pragma unroll 2
        for (int i = tid; i < ROWS_TILE * 16; i += TPB) {
            const int r = i >> 4, s = i & 15;
            const int row = row0 + r;
            float4 v0, v1;
            if (row < N) {
                const float4* p = (const float4*)x + (size_t)row * 32 + s * 2;
                v0 = __ldg(p); v1 = __ldg(p + 1);
            } else {
                v0 = make_float4(0.f, 0.f, 0.f, 0.f); v1 = v0;
            }
            uint4 hx, hq;
            hx.x = h2pack(v0.x, v0.y); hx.y = h2pack(v0.z, v0.w);
            hx.z = h2pack(v1.x, v1.y); hx.w = h2pack(v1.z, v1.w);
            hq.x = h2pack(v0.x * v0.x, v0.y * v0.y);
            hq.y = h2pack(v0.z * v0.z, v0.w * v0.w);
            hq.z = h2pack(v1.x * v1.x, v1.y * v1.y);
            hq.w = h2pack(v1.z * v1.z, v1.w * v1.w);
            const uint32_t off = r * 256 + ((s ^ (r & 7)) << 4);
            *(uint4*)(smc + SM_X  + off) = hx;
            *(uint4*)(smc + SM_X2 + off) = hq;
        }
        __syncthreads();

        // ---- GEMM: acc[mt][g][hi][4]; g: 0=s2, 1..4=z, 5=s1 ---------------
        float acc[2][6][2][4];
#pragma unroll
        for (int mt = 0; mt < 2; mt++)
#pragma unroll
            for (int g = 0; g < 6; g++)
#pragma unroll
                for (int hi = 0; hi < 2; hi++)
#pragma unroll
                    for (int e = 0; e < 4; e++) acc[mt][g][hi][e] = 0.f;

#pragma unroll
        for (int ch = 0; ch < 8; ch++) {
            const uint32_t xa = (((uint32_t)(ch * 2 + (mat >> 1))) ^ (uint32_t)rin) << 4;
            const uint32_t xb = (((uint32_t)(ch * 2 + (mat & 1)))  ^ (uint32_t)rin) << 4;

            uint32_t ax[2][4];
            ldsm4(ax[0], a_pre[0] + xa);
            ldsm4(ax[1], a_pre[1] + xa);

#pragma unroll
            for (int g = 0; g < 5; g++) {
                uint32_t b[4];
                ldsm4(b, b_pre + (uint32_t)g * 8192u + xb);
                mma16816(acc[0][g][0], ax[0], b[0], b[1]);
                mma16816(acc[1][g][0], ax[1], b[0], b[1]);
                mma16816(acc[0][g][1], ax[0], b[2], b[3]);
                mma16816(acc[1][g][1], ax[1], b[2], b[3]);
            }

            uint32_t aq[2][4];
            ldsm4(aq[0], a2_pre[0] + xa);
            ldsm4(aq[1], a2_pre[1] + xa);
            {
                uint32_t b[4];
                ldsm4(b, b_pre + 5u * 8192u + xb);
                mma16816(acc[0][5][0], aq[0], b[0], b[1]);
                mma16816(acc[1][5][0], aq[1], b[0], b[1]);
                mma16816(acc[0][5][1], aq[0], b[2], b[3]);
                mma16816(acc[1][5][1], aq[1], b[2], b[3]);
            }
        }

        // ---- partial epilogue: 4 comps/thread/row, butterfly over qc ------
        float pmx[2][2], psum[2][2];
#pragma unroll
        for (int mt = 0; mt < 2; mt++) {
#pragma unroll
            for (int h = 0; h < 2; h++) {
                float ll[4];
#pragma unroll
                for (int hi = 0; hi < 2; hi++) {
#pragma unroll
                    for (int p = 0; p < 2; p++) {
                        const int k = wk * 16 + hi * 8 + 2 * qc + p;
                        const int e = 2 * h + p;
                        float v = cst[k] + acc[mt][0][hi][e]
                                - 0.5f * acc[mt][5][hi][e];
#pragma unroll
                        for (int jj = 0; jj < 4; jj++) {
                            const float z = acc[mt][1 + jj][hi][e]
                                          - cst[32 + 32 * jj + k];
                            v = fmaf(0.5f * z, z, v);
                        }
                        ll[hi * 2 + p] = v;
                    }
                }
                float mx = fmaxf(fmaxf(ll[0], ll[1]), fmaxf(ll[2], ll[3]));
                float sum = __expf(ll[0] - mx) + __expf(ll[1] - mx)
                          + __expf(ll[2] - mx) + __expf(ll[3] - mx);
#pragma unroll
                for (int off = 1; off <= 2; off <<= 1) {
                    const float m2 = __shfl_xor_sync(0xffffffffu, mx,  off);
                    const float s2 = __shfl_xor_sync(0xffffffffu, sum, off);
                    const float nm = fmaxf(mx, m2);
                    sum = sum * __expf(mx - nm) + s2 * __expf(m2 - nm);
                    mx = nm;
                }
                pmx[mt][h] = mx; psum[mt][h] = sum;
            }
        }

        __syncthreads();   // all x/x2 smem reads done -> safe to write alias
#pragma unroll
        for (int mt = 0; mt < 2; mt++)
#pragma unroll
            for (int h = 0; h < 2; h++)
                if (qc == 0)
                    sP[wk * 128 + wm * 32 + mt * 16 + qr + 8 * h]
                        = make_float2(pmx[mt][h], psum[mt][h]);
        __syncthreads();

        // ---- combine the two component halves, write out ------------------
        if (tid < 128) {
            const float2 a = sP[tid];
            const float2 b = sP[128 + tid];
            const float m = fmaxf(a.x, b.x);
            const float s = a.y * __expf(a.x - m) + b.y * __expf(b.x - m);
            const int row = row0 + tid;
            if (row < N) out[row] = m + logf(s);
        }
        __syncthreads();   // sP reads done before next tile load overwrites
    }
}

// ---------------------------------------------------------------------------
extern "C" void kernel_launch(void* const* d_in, const int* in_sizes, int n_in,
                              void* d_out, int out_size)
{
    const float* x  = (const float*)d_in[0];
    const float* MU = (const float*)d_in[1];
    const float* A  = (const float*)d_in[2];
    const float* Dm = (const float*)d_in[3];
    const float* PI = (const float*)d_in[4];
    float* out = (float*)d_out;

    const int N = in_sizes[0] / DDIM;
    const int ntiles = (N + ROWS_TILE - 1) / ROWS_TILE;

    int nsm = 148;
    cudaDeviceGetAttribute(&nsm, cudaDevAttrMultiProcessorCount, 0);
    if (nsm <= 0) nsm = 148;
    int grid = 2 * nsm;
    if (grid > ntiles) grid = ntiles;

    cudaFuncSetAttribute(mfa_mma, cudaFuncAttributeMaxDynamicSharedMemorySize,
                         SMEM_TOTAL);

    mfa_precompute<<<KCOMP, 32>>>(MU, A, Dm, PI);
    mfa_mma<<<grid, TPB, SMEM_TOTAL>>>(x, out, N, ntiles);
}

// round 7
// speedup vs baseline: 12.2204x; 1.0986x over previous
#include <cuda_runtime.h>
#include <math.h>
#include <float.h>
#include <stdint.h>
#include <cuda_fp16.h>

#define KCOMP 32
#define DDIM  128
#define LDIM  4
#define TPB   256
#define ROWS_TILE 128

// smem byte offsets (~84KB total, 2 CTAs/SM)
#define SM_X   0        // x tile: 128 rows x 256B (fp16) = 32768
#define SM_W   32768    // weights: 192 rows x 256B (fp16) = 49152
#define SM_C   81920    // cst[32] + bm[4][32] floats = 640
#define SM_P   82560    // sP: 256 float2 = 2048
#define SMEM_TOTAL 84608

// ---- device globals -------------------------------------------------------
__device__ uint4  g_Wh[192 * 16];      // fp16 weights, row n: 128 halves
__device__ float  g_cst[KCOMP];
__device__ float4 g_bm[KCOMP];

// ---- helpers --------------------------------------------------------------
__device__ __forceinline__ uint32_t h2pack(float a, float b) {
    __half2 h = __floats2half2_rn(a, b);
    return *(uint32_t*)&h;
}
__device__ __forceinline__ uint32_t smem_u32(const void* p) {
    uint32_t a;
    asm("{ .reg .u64 t; cvta.to.shared.u64 t, %1; cvt.u32.u64 %0, t; }" : "=r"(a) : "l"(p));
    return a;
}
__device__ __forceinline__ void mma16816(float c[4], const uint32_t a[4],
                                         uint32_t b0, uint32_t b1) {
    asm volatile(
        "mma.sync.aligned.m16n8k16.row.col.f32.f16.f16.f32 "
        "{%0,%1,%2,%3}, {%4,%5,%6,%7}, {%8,%9}, {%0,%1,%2,%3};"
        : "+f"(c[0]), "+f"(c[1]), "+f"(c[2]), "+f"(c[3])
        : "r"(a[0]), "r"(a[1]), "r"(a[2]), "r"(a[3]), "r"(b0), "r"(b1));
}
__device__ __forceinline__ void ldsm4(uint32_t r[4], uint32_t addr) {
    asm volatile("ldmatrix.sync.aligned.m8n8.x4.shared.b16 {%0,%1,%2,%3}, [%4];"
        : "=r"(r[0]), "=r"(r[1]), "=r"(r[2]), "=r"(r[3]) : "r"(addr));
}
__device__ __forceinline__ uint32_t sq2(uint32_t a) {
    __half2 h = *(__half2*)&a;
    h = __hmul2(h, h);
    return *(uint32_t*)&h;
}

// ---------------------------------------------------------------------------
// Stage A: per-component precompute. 32 blocks x 1 warp; fp32 throughout.
// ---------------------------------------------------------------------------
__global__ void mfa_precompute(const float* __restrict__ MU,
                               const float* __restrict__ A,
                               const float* __restrict__ Dm,
                               const float* __restrict__ PI)
{
    const int k    = blockIdx.x;
    const int lane = threadIdx.x;

    float s[22];
#pragma unroll
    for (int j = 0; j < 22; j++) s[j] = 0.f;

#pragma unroll
    for (int i = 0; i < 4; i++) {
        const int d = lane + 32 * i;
        const float Dv = Dm[k * DDIM + d];
        const float iD = 1.0f / (Dv * Dv);
        const float mu = MU[k * DDIM + d];
        float a[LDIM], B[LDIM];
#pragma unroll
        for (int l = 0; l < LDIM; l++) {
            a[l] = A[(k * DDIM + d) * LDIM + l];
            B[l] = iD * a[l];
        }
        int idx = 0;
#pragma unroll
        for (int l = 0; l < LDIM; l++)
#pragma unroll
            for (int m = 0; m < LDIM; m++)
                s[idx++] += a[l] * B[m];
#pragma unroll
        for (int m = 0; m < LDIM; m++)
            s[idx++] += mu * B[m];
        s[20] += iD * mu * mu;
        s[21] += 2.0f * logf(Dv);
    }

#pragma unroll
    for (int j = 0; j < 22; j++)
#pragma unroll
        for (int o = 16; o; o >>= 1)
            s[j] += __shfl_xor_sync(0xffffffffu, s[j], o);

    float Lm[LDIM][LDIM], bmu[LDIM];
#pragma unroll
    for (int l = 0; l < LDIM; l++)
#pragma unroll
        for (int m = 0; m < LDIM; m++)
            Lm[l][m] = s[l * LDIM + m] + (l == m ? 1.0f : 0.0f);
#pragma unroll
    for (int m = 0; m < LDIM; m++) bmu[m] = s[16 + m];
    const float tc  = s[20];
    const float sld = s[21];

    float G[LDIM][LDIM] = {};
#pragma unroll
    for (int i = 0; i < LDIM; i++) {
#pragma unroll
        for (int j = 0; j <= i; j++) {
            float v = Lm[i][j];
#pragma unroll
            for (int p = 0; p < LDIM; p++)
                if (p < j) v -= G[i][p] * G[j][p];
            if (i == j) G[i][i] = sqrtf(v);
            else        G[i][j] = v / G[j][j];
        }
    }
    float logdetL = 0.f;
#pragma unroll
    for (int i = 0; i < LDIM; i++) logdetL += 2.0f * logf(G[i][i]);

    float U[LDIM][LDIM] = {};
#pragma unroll
    for (int j = 0; j < LDIM; j++) {
        U[j][j] = 1.0f / G[j][j];
#pragma unroll
        for (int i = 0; i < LDIM; i++) {
            if (i > j) {
                float v = 0.f;
#pragma unroll
                for (int p = 0; p < LDIM; p++)
                    if (p >= j && p < i) v += G[i][p] * U[p][j];
                U[i][j] = -v / G[i][i];
            }
        }
    }

    if (lane == 0) {
        const float LOG2PI = 1.8378770664093454835606594728112f;
        g_cst[k] = PI[k] - 0.5f * ((float)DDIM * LOG2PI + logdetL + sld + tc);
        float bp[LDIM];
#pragma unroll
        for (int l = 0; l < LDIM; l++) {
            float v = 0.f;
#pragma unroll
            for (int m = 0; m <= l; m++) v += U[l][m] * bmu[m];
            bp[l] = v;
        }
        g_bm[k] = make_float4(bp[0], bp[1], bp[2], bp[3]);
    }

    __half* Wh = (__half*)g_Wh;
#pragma unroll
    for (int i = 0; i < 4; i++) {
        const int d = lane + 32 * i;
        const float Dv = Dm[k * DDIM + d];
        const float iD = 1.0f / (Dv * Dv);
        const float mu = MU[k * DDIM + d];
        float B[LDIM];
#pragma unroll
        for (int l = 0; l < LDIM; l++)
            B[l] = iD * A[(k * DDIM + d) * LDIM + l];
        float Bp[LDIM];
#pragma unroll
        for (int l = 0; l < LDIM; l++) {
            float v = 0.f;
#pragma unroll
            for (int m = 0; m <= l; m++) v += U[l][m] * B[m];
            Bp[l] = v;
        }
        Wh[(size_t)k * DDIM + d] = __float2half_rn(iD * mu);
#pragma unroll
        for (int j = 0; j < LDIM; j++)
            Wh[(size_t)(32 + 32 * j + k) * DDIM + d] = __float2half_rn(Bp[j]);
        Wh[(size_t)(160 + k) * DDIM + d] = __float2half_rn(iD);
    }
}

// ---------------------------------------------------------------------------
// Stage B: persistent mma.sync kernel. 8 warps: (wm rows-32) x (wk comp-16).
// x^2 fragments computed in registers (HMUL2 of x fragments) — no x^2 tile.
// ---------------------------------------------------------------------------
__global__ void __launch_bounds__(TPB, 2)
mfa_mma(const float* __restrict__ x, float* __restrict__ out, int N, int ntiles)
{
    extern __shared__ char smc[];
    const int tid  = threadIdx.x;
    const int lane = tid & 31;
    const int w    = tid >> 5;
    const int wm   = w & 3;         // row group (32 rows)
    const int wk   = w >> 2;        // component half (16 comps)
    const int qr   = lane >> 2;     // 0..7
    const int qc   = lane & 3;      // 0..3
    const int rin  = lane & 7;
    const int mat  = lane >> 3;     // 0..3

    const uint32_t sb = smem_u32(smc);
    float2* sP = (float2*)(smc + SM_P);

    // ---- load weights to smem once (persistent) ---------------------------
    for (int i = tid; i < 192 * 16; i += TPB) {
        const int r = i >> 4, s = i & 15;
        uint4 v = g_Wh[i];
        *(uint4*)(smc + SM_W + r * 256 + ((s ^ (r & 7)) << 4)) = v;
    }
    {
        float* c = (float*)(smc + SM_C);
        if (tid < 32) {
            c[tid] = g_cst[tid];
            float4 b = g_bm[tid];
            c[32 + tid] = b.x; c[64 + tid] = b.y;
            c[96 + tid] = b.z; c[128 + tid] = b.w;
        }
    }
    __syncthreads();

    const float* cst = (const float*)(smc + SM_C);

    uint32_t a_pre[2];
#pragma unroll
    for (int mt = 0; mt < 2; mt++) {
        const uint32_t row = (uint32_t)(wm * 32 + mt * 16 + (mat & 1) * 8 + rin);
        a_pre[mt] = sb + SM_X + row * 256u;
    }
    const uint32_t b_pre = sb + SM_W
        + (uint32_t)(wk * 16 + (mat >> 1) * 8 + rin) * 256u;

    for (int tile = blockIdx.x; tile < ntiles; tile += gridDim.x) {
        const int row0 = tile * ROWS_TILE;

        // ---- load x tile (fp16) -------------------------------------------
#pragma unroll 2
        for (int i = tid; i < ROWS_TILE * 16; i += TPB) {
            const int r = i >> 4, s = i & 15;
            const int row = row0 + r;
            float4 v0, v1;
            if (row < N) {
                const float4* p = (const float4*)x + (size_t)row * 32 + s * 2;
                v0 = __ldg(p); v1 = __ldg(p + 1);
            } else {
                v0 = make_float4(0.f, 0.f, 0.f, 0.f); v1 = v0;
            }
            uint4 hx;
            hx.x = h2pack(v0.x, v0.y); hx.y = h2pack(v0.z, v0.w);
            hx.z = h2pack(v1.x, v1.y); hx.w = h2pack(v1.z, v1.w);
            *(uint4*)(smc + SM_X + r * 256 + ((s ^ (r & 7)) << 4)) = hx;
        }
        __syncthreads();

        // ---- GEMM: acc[mt][g][hi][4]; g: 0=s2, 1..4=z, 5=s1 ---------------
        float acc[2][6][2][4];
#pragma unroll
        for (int mt = 0; mt < 2; mt++)
#pragma unroll
            for (int g = 0; g < 6; g++)
#pragma unroll
                for (int hi = 0; hi < 2; hi++)
#pragma unroll
                    for (int e = 0; e < 4; e++) acc[mt][g][hi][e] = 0.f;

#pragma unroll
        for (int ch = 0; ch < 8; ch++) {
            const uint32_t xa = (((uint32_t)(ch * 2 + (mat >> 1))) ^ (uint32_t)rin) << 4;
            const uint32_t xb = (((uint32_t)(ch * 2 + (mat & 1)))  ^ (uint32_t)rin) << 4;

            uint32_t ax[2][4];
            ldsm4(ax[0], a_pre[0] + xa);
            ldsm4(ax[1], a_pre[1] + xa);

#pragma unroll
            for (int g = 0; g < 5; g++) {
                uint32_t b[4];
                ldsm4(b, b_pre + (uint32_t)g * 8192u + xb);
                mma16816(acc[0][g][0], ax[0], b[0], b[1]);
                mma16816(acc[1][g][0], ax[1], b[0], b[1]);
                mma16816(acc[0][g][1], ax[0], b[2], b[3]);
                mma16816(acc[1][g][1], ax[1], b[2], b[3]);
            }

            // x^2 fragments in registers (same layout, elementwise square)
            uint32_t aq[2][4];
#pragma unroll
            for (int j = 0; j < 4; j++) {
                aq[0][j] = sq2(ax[0][j]);
                aq[1][j] = sq2(ax[1][j]);
            }
            {
                uint32_t b[4];
                ldsm4(b, b_pre + 5u * 8192u + xb);
                mma16816(acc[0][5][0], aq[0], b[0], b[1]);
                mma16816(acc[1][5][0], aq[1], b[0], b[1]);
                mma16816(acc[0][5][1], aq[0], b[2], b[3]);
                mma16816(acc[1][5][1], aq[1], b[2], b[3]);
            }
        }

        // ---- partial epilogue: common max, then exp ------------------------
#pragma unroll
        for (int mt = 0; mt < 2; mt++) {
#pragma unroll
            for (int h = 0; h < 2; h++) {
                float ll[4];
#pragma unroll
                for (int hi = 0; hi < 2; hi++) {
#pragma unroll
                    for (int p = 0; p < 2; p++) {
                        const int k = wk * 16 + hi * 8 + 2 * qc + p;
                        const int e = 2 * h + p;
                        float v = cst[k] + acc[mt][0][hi][e]
                                - 0.5f * acc[mt][5][hi][e];
#pragma unroll
                        for (int jj = 0; jj < 4; jj++) {
                            const float z = acc[mt][1 + jj][hi][e]
                                          - cst[32 + 32 * jj + k];
                            v = fmaf(0.5f * z, z, v);
                        }
                        ll[hi * 2 + p] = v;
                    }
                }
                float mx = fmaxf(fmaxf(ll[0], ll[1]), fmaxf(ll[2], ll[3]));
#pragma unroll
                for (int off = 1; off <= 2; off <<= 1)
                    mx = fmaxf(mx, __shfl_xor_sync(0xffffffffu, mx, off));
                float sum = __expf(ll[0] - mx) + __expf(ll[1] - mx)
                          + __expf(ll[2] - mx) + __expf(ll[3] - mx);
#pragma unroll
                for (int off = 1; off <= 2; off <<= 1)
                    sum += __shfl_xor_sync(0xffffffffu, sum, off);

                if (qc == 0)
                    sP[wk * 128 + wm * 32 + mt * 16 + qr + 8 * h]
                        = make_float2(mx, sum);
            }
        }
        __syncthreads();

        // ---- combine the two component halves, write out ------------------
        if (tid < 128) {
            const float2 a = sP[tid];
            const float2 b = sP[128 + tid];
            const float m = fmaxf(a.x, b.x);
            const float s = a.y * __expf(a.x - m) + b.y * __expf(b.x - m);
            const int row = row0 + tid;
            if (row < N) out[row] = m + __logf(s);
        }
    }
}

// ---------------------------------------------------------------------------
extern "C" void kernel_launch(void* const* d_in, const int* in_sizes, int n_in,
                              void* d_out, int out_size)
{
    const float* x  = (const float*)d_in[0];
    const float* MU = (const float*)d_in[1];
    const float* A  = (const float*)d_in[2];
    const float* Dm = (const float*)d_in[3];
    const float* PI = (const float*)d_in[4];
    float* out = (float*)d_out;

    const int N = in_sizes[0] / DDIM;
    const int ntiles = (N + ROWS_TILE - 1) / ROWS_TILE;

    int nsm = 148;
    cudaDeviceGetAttribute(&nsm, cudaDevAttrMultiProcessorCount, 0);
    if (nsm <= 0) nsm = 148;
    int grid = 2 * nsm;
    if (grid > ntiles) grid = ntiles;

    cudaFuncSetAttribute(mfa_mma, cudaFuncAttributeMaxDynamicSharedMemorySize,
                         SMEM_TOTAL);

    mfa_precompute<<<KCOMP, 32>>>(MU, A, Dm, PI);
    mfa_mma<<<grid, TPB, SMEM_TOTAL>>>(x, out, N, ntiles);
}